// round 5
// baseline (speedup 1.0000x reference)
#include <cuda_runtime.h>
#include <cstdint>
#include <cstddef>

// Problem constants
#define NNODES 10000
#define DFEAT  128
#define KTOP   8
#define ROWI4  2500          // 10000 int32 / 4 per row
#define OUTCH  128
#define LOUT   120           // D - K
#define CT     81            // 9 channels * 9 taps
#define NPAIR  8             // o-pairs per thread (O_BLK = 16)
#define NOG    8             // o groups (8 * 16 = 128)
#define WBLK   4             // w per thread
#define NWG    30            // w groups (30 * 4 = 120)
#define WPAD   9             // padded float2 stride per (c,t,og) chunk (8 used + 1 pad)

// Packed weights: for (c,t,og,p): float2 = (W[og*16+2p][c][t], W[og*16+2p+1][c][t])
__device__ float2 g_wpack[CT * NOG * NPAIR];   // 5184 float2 = 41.5 KB

__global__ void pack_weights_kernel(const float* __restrict__ w) {
    int i = blockIdx.x * blockDim.x + threadIdx.x;
    if (i >= CT * NOG * NPAIR) return;
    int p  = i & 7;
    int og = (i >> 3) & 7;
    int ct = i >> 6;                 // 0..80
    int c  = ct / 9;
    int t  = ct - c * 9;
    int o  = (og << 4) + (p << 1);
    float lo = w[o * 81 + c * 9 + t];
    float hi = w[(o + 1) * 81 + c * 9 + t];
    g_wpack[i] = make_float2(lo, hi);
}

// packed fp32x2 FMA: d = a*b + d (lanewise on the two f32 halves)
#define FMA2(d, a, b) asm("fma.rn.f32x2 %0, %1, %2, %0;" : "+l"(d) : "l"(a), "l"(b))

// branchless sorted-descending top-8 insert (bubble step keeps tk sorted desc)
#define TK_INSERT(val) do {                           \
    float _v = (val);                                 \
    _Pragma("unroll")                                 \
    for (int _i = 0; _i < KTOP; _i++) {               \
        float _mx = fmaxf(tk[_i], _v);                \
        _v = fminf(tk[_i], _v);                       \
        tk[_i] = _mx;                                 \
    }                                                 \
} while (0)

extern __shared__ unsigned char smem_raw[];

__global__ __launch_bounds__(256, 2)
void lgcl_fused_kernel(const float* __restrict__ nf,
                       const int*   __restrict__ adj,
                       const float* __restrict__ bias,
                       float*       __restrict__ out) {
    // ---- shared memory layout ----
    float2* wpad = (float2*)smem_raw;               // CT*NOG*WPAD = 5832 f2 (46.6 KB)
    float2* selp = wpad + CT * NOG * WPAD;          // 9 * 128 f2 duplicated sel (9.2 KB)
    int*    snbr = (int*)(selp + 9 * DFEAT);        // 64 ints
    int*    scnt = snbr + 64;

    const int tid = threadIdx.x;
    const int n   = blockIdx.x;

    if (tid == 0) *scnt = 0;

    // ---- stage padded packed weights into smem (conflict-free layout) ----
    for (int i = tid; i < CT * NOG * NPAIR; i += 256) {
        int p = i & 7;
        int base = i >> 3;           // (ct*8 + og)
        wpad[base * WPAD + p] = g_wpack[i];
    }
    __syncthreads();

    // ---- scan adjacency row: collect neighbor column indices ----
    const int4* row = (const int4*)(adj + (size_t)n * (size_t)NNODES);
    for (int i = tid; i < ROWI4; i += 256) {
        int4 q = row[i];
        if (q.x | q.y | q.z | q.w) {
            if (q.x) { int s = atomicAdd(scnt, 1); if (s < 64) snbr[s] = (i << 2); }
            if (q.y) { int s = atomicAdd(scnt, 1); if (s < 64) snbr[s] = (i << 2) + 1; }
            if (q.z) { int s = atomicAdd(scnt, 1); if (s < 64) snbr[s] = (i << 2) + 2; }
            if (q.w) { int s = atomicAdd(scnt, 1); if (s < 64) snbr[s] = (i << 2) + 3; }
        }
    }
    __syncthreads();
    int cnt = *scnt;
    if (cnt > 64) cnt = 64;

    // ---- per-feature top-8 over neighbors, build duplicated sel in smem ----
    if (tid < DFEAT) {
        const int f = tid;
        const float NEG_INF = __int_as_float(0xff800000u);
        float tk[KTOP];
        #pragma unroll
        for (int r = 0; r < KTOP; r++) tk[r] = NEG_INF;

        int j = 0;
        for (; j + 4 <= cnt; j += 4) {
            int i0 = snbr[j], i1 = snbr[j + 1], i2 = snbr[j + 2], i3 = snbr[j + 3];
            float v0 = __ldg(nf + (size_t)i0 * DFEAT + f);
            float v1 = __ldg(nf + (size_t)i1 * DFEAT + f);
            float v2 = __ldg(nf + (size_t)i2 * DFEAT + f);
            float v3 = __ldg(nf + (size_t)i3 * DFEAT + f);
            TK_INSERT(v0); TK_INSERT(v1); TK_INSERT(v2); TK_INSERT(v3);
        }
        for (; j < cnt; j++) {
            float v = __ldg(nf + (size_t)snbr[j] * DFEAT + f);
            TK_INSERT(v);
        }
        // reference semantics: missing neighbors contribute zero rows before topk
        for (int z = cnt; z < KTOP; z++) { TK_INSERT(0.0f); }

        float sv = nf[(size_t)n * DFEAT + f];
        selp[f] = make_float2(sv, sv);                       // channel 0 = self
        #pragma unroll
        for (int r = 0; r < KTOP; r++)                       // channels 1..8 desc
            selp[(r + 1) * DFEAT + f] = make_float2(tk[r], tk[r]);
    }
    __syncthreads();

    // ---- conv: register-tiled, packed f32x2 FMAs ----
    if (tid < NOG * NWG) {
        const int og = tid & 7;      // 8 o-groups of 16 channels
        const int wg = tid >> 3;     // 30 w-groups of 4 positions
        const int w0 = wg << 2;

        unsigned long long acc[NPAIR][WBLK];
        #pragma unroll
        for (int p = 0; p < NPAIR; p++)
            #pragma unroll
            for (int w = 0; w < WBLK; w++)
                acc[p][w] = 0ull;

        const unsigned long long* selq = (const unsigned long long*)selp;
        const unsigned long long* wq   = (const unsigned long long*)wpad;

        #pragma unroll 1
        for (int c = 0; c < 9; c++) {
            unsigned long long ss[12];
            #pragma unroll
            for (int i = 0; i < 12; i++)
                ss[i] = selq[c * DFEAT + w0 + i];
            #pragma unroll
            for (int t = 0; t < 9; t++) {
                const unsigned long long* wt = wq + ((c * 9 + t) * NOG + og) * WPAD;
                unsigned long long wv[NPAIR];
                #pragma unroll
                for (int p = 0; p < NPAIR; p++) wv[p] = wt[p];
                #pragma unroll
                for (int p = 0; p < NPAIR; p++) {
                    #pragma unroll
                    for (int w = 0; w < WBLK; w++)
                        FMA2(acc[p][w], wv[p], ss[t + w]);
                }
            }
        }

        // ---- epilogue: add bias, store 16 x STG.128 ----
        float* outp = out + (size_t)n * (size_t)(OUTCH * LOUT);
        #pragma unroll
        for (int p = 0; p < NPAIR; p++) {
            int o = (og << 4) + (p << 1);
            float blo = __ldg(bias + o);
            float bhi = __ldg(bias + o + 1);
            float4 rlo, rhi;
            rlo.x = __uint_as_float((unsigned)(acc[p][0]      )) + blo;
            rlo.y = __uint_as_float((unsigned)(acc[p][1]      )) + blo;
            rlo.z = __uint_as_float((unsigned)(acc[p][2]      )) + blo;
            rlo.w = __uint_as_float((unsigned)(acc[p][3]      )) + blo;
            rhi.x = __uint_as_float((unsigned)(acc[p][0] >> 32)) + bhi;
            rhi.y = __uint_as_float((unsigned)(acc[p][1] >> 32)) + bhi;
            rhi.z = __uint_as_float((unsigned)(acc[p][2] >> 32)) + bhi;
            rhi.w = __uint_as_float((unsigned)(acc[p][3] >> 32)) + bhi;
            *(float4*)(outp + (size_t)o * LOUT + w0)       = rlo;
            *(float4*)(outp + (size_t)(o + 1) * LOUT + w0) = rhi;
        }
    }
}

extern "C" void kernel_launch(void* const* d_in, const int* in_sizes, int n_in,
                              void* d_out, int out_size) {
    const float* nf  = (const float*)d_in[0];   // node_features [10000,128] f32
    const int*   adj = (const int*)d_in[1];     // adj_matrix [10000,10000] i32
    const float* w   = (const float*)d_in[2];   // conv_w [128,9,9] f32
    const float* b   = (const float*)d_in[3];   // conv_b [128] f32
    float* out = (float*)d_out;                 // [10000,128,120] f32

    pack_weights_kernel<<<(CT * NOG * NPAIR + 255) / 256, 256>>>(w);

    const int smem_bytes = (CT * NOG * WPAD + 9 * DFEAT) * (int)sizeof(float2)
                         + 65 * (int)sizeof(int) + 16;
    cudaFuncSetAttribute(lgcl_fused_kernel,
                         cudaFuncAttributeMaxDynamicSharedMemorySize, smem_bytes);
    lgcl_fused_kernel<<<NNODES, 256, smem_bytes>>>(nf, adj, b, out);
}

// round 7
// speedup vs baseline: 1.2990x; 1.2990x over previous
#include <cuda_runtime.h>
#include <cstdint>
#include <cstddef>

// Problem constants
#define NNODES 10000
#define DFEAT  128
#define KTOP   8
#define ROWI4  2500          // 10000 int32 / 4 per row
#define OUTCH  128
#define LOUT   120           // D - K
#define CT     81            // 9 channels * 9 taps
#define NPAIRS 64            // o-pairs total (128 channels / 2)
#define WBLK   12            // w positions per thread
#define NWG    10            // w groups (10 * 12 = 120)
#define CONV_THREADS 640     // 20 warps = 2 pair-halves x 10 w-groups

typedef unsigned long long ull;

// Packed weights: [ct][pair] : float2 = (W[2p][ct], W[2p+1][ct]), ct = c*9+t
__device__ float2 g_wpack[CT * NPAIRS];           // 5184 float2 = 41.5 KB

// sel scratch: [node][9][128] float  (46 MB)
__device__ float g_sel[(size_t)NNODES * 9 * DFEAT];

__global__ void pack_weights_kernel(const float* __restrict__ w) {
    int i = blockIdx.x * blockDim.x + threadIdx.x;
    if (i >= CT * NPAIRS) return;
    int p  = i & 63;
    int ct = i >> 6;                  // 0..80  (= c*9 + t)
    g_wpack[i] = make_float2(w[(2 * p) * CT + ct], w[(2 * p + 1) * CT + ct]);
}

// packed fp32x2 FMA: d = a*b + d (lanewise on the two f32 halves)
#define FMA2(d, a, b) asm("fma.rn.f32x2 %0, %1, %2, %0;" : "+l"(d) : "l"(a), "l"(b))

// branchless sorted-descending top-8 insert
#define TK_INSERT(val) do {                           \
    float _v = (val);                                 \
    _Pragma("unroll")                                 \
    for (int _i = 0; _i < KTOP; _i++) {               \
        float _mx = fmaxf(tk[_i], _v);                \
        _v = fminf(tk[_i], _v);                       \
        tk[_i] = _mx;                                 \
    }                                                 \
} while (0)

// ---------------------------------------------------------------------------
// Kernel 2: adjacency scan + per-feature top-8 -> g_sel[node][9][128]
// 2 nodes per block, 256 threads (128 per node). High occupancy, tiny smem.
// ---------------------------------------------------------------------------
__global__ __launch_bounds__(256)
void gather_topk_kernel(const float* __restrict__ nf,
                        const int*   __restrict__ adj) {
    __shared__ int snbr[2][64];
    __shared__ int scnt[2];

    const int tid  = threadIdx.x;
    const int half = tid >> 7;          // 0/1 : which node of the pair
    const int lt   = tid & 127;
    const int n    = blockIdx.x * 2 + half;

    if (lt == 0) scnt[half] = 0;
    __syncthreads();

    // scan this node's adjacency row (128 threads, coalesced int4)
    const int4* row = (const int4*)(adj + (size_t)n * NNODES);
    for (int i = lt; i < ROWI4; i += 128) {
        int4 q = row[i];
        if (q.x | q.y | q.z | q.w) {
            if (q.x) { int s = atomicAdd(&scnt[half], 1); if (s < 64) snbr[half][s] = (i << 2); }
            if (q.y) { int s = atomicAdd(&scnt[half], 1); if (s < 64) snbr[half][s] = (i << 2) + 1; }
            if (q.z) { int s = atomicAdd(&scnt[half], 1); if (s < 64) snbr[half][s] = (i << 2) + 2; }
            if (q.w) { int s = atomicAdd(&scnt[half], 1); if (s < 64) snbr[half][s] = (i << 2) + 3; }
        }
    }
    __syncthreads();

    int cnt = scnt[half];
    if (cnt > 64) cnt = 64;

    // per-feature top-8 (thread = one feature column)
    const int f = lt;
    const float NEG_INF = __int_as_float(0xff800000u);
    float tk[KTOP];
    #pragma unroll
    for (int r = 0; r < KTOP; r++) tk[r] = NEG_INF;

    int j = 0;
    for (; j + 4 <= cnt; j += 4) {
        int i0 = snbr[half][j], i1 = snbr[half][j + 1];
        int i2 = snbr[half][j + 2], i3 = snbr[half][j + 3];
        float v0 = __ldg(nf + (size_t)i0 * DFEAT + f);
        float v1 = __ldg(nf + (size_t)i1 * DFEAT + f);
        float v2 = __ldg(nf + (size_t)i2 * DFEAT + f);
        float v3 = __ldg(nf + (size_t)i3 * DFEAT + f);
        TK_INSERT(v0); TK_INSERT(v1); TK_INSERT(v2); TK_INSERT(v3);
    }
    for (; j < cnt; j++) {
        float v = __ldg(nf + (size_t)snbr[half][j] * DFEAT + f);
        TK_INSERT(v);
    }
    // reference semantics: missing neighbors contribute zero rows before topk
    for (int z = cnt; z < KTOP; z++) { TK_INSERT(0.0f); }

    float* selrow = g_sel + (size_t)n * (9 * DFEAT);
    selrow[f] = nf[(size_t)n * DFEAT + f];            // channel 0 = self
    #pragma unroll
    for (int r = 0; r < KTOP; r++)                    // channels 1..8 desc
        selrow[(r + 1) * DFEAT + f] = tk[r];
}

// ---------------------------------------------------------------------------
// Kernel 3: conv. 2 nodes per block, 640 threads (20 warps).
// warp = (pair-half og2, w-group wg); thread = 1 o-pair x 12 w positions.
// Weight LDS.64: 32 consecutive float2 per warp (conflict-free, 256B).
// sel LDS.64: full-warp broadcast.
// ---------------------------------------------------------------------------
extern __shared__ unsigned char smraw[];

__global__ __launch_bounds__(CONV_THREADS, 1)
void conv_kernel(const float* __restrict__ bias,
                 float*       __restrict__ out) {
    float2* sw   = (float2*)smraw;                    // [CT*64]   41.5 KB
    float2* ssel = sw + CT * NPAIRS;                  // [2][9*128] dup. 18.4 KB

    const int tid = threadIdx.x;
    const int n0  = blockIdx.x * 2;

    // stage packed weights
    for (int i = tid; i < CT * NPAIRS; i += CONV_THREADS)
        sw[i] = g_wpack[i];
    // stage sel for both nodes, duplicated to float2
    for (int i = tid; i < 2 * 9 * DFEAT; i += CONV_THREADS) {
        int nd = i / (9 * DFEAT);
        int j  = i - nd * (9 * DFEAT);
        float v = g_sel[(size_t)(n0 + nd) * (9 * DFEAT) + j];
        ssel[i] = make_float2(v, v);
    }
    __syncthreads();

    const int lane = tid & 31;
    const int warp = tid >> 5;          // 0..19
    const int og2  = warp & 1;          // pair half
    const int wg   = warp >> 1;         // 0..9
    const int pair = og2 * 32 + lane;   // 0..63
    const int o    = pair * 2;
    const int w0   = wg * WBLK;

    const ull* wq = (const ull*)sw;
    const float blo = __ldg(bias + o);
    const float bhi = __ldg(bias + o + 1);

    #pragma unroll 1
    for (int nd = 0; nd < 2; nd++) {
        const ull* selq = (const ull*)(ssel + nd * (9 * DFEAT));

        ull acc[WBLK];
        #pragma unroll
        for (int w = 0; w < WBLK; w++) acc[w] = 0ull;

        #pragma unroll 1
        for (int c = 0; c < 9; c++) {
            ull ss[WBLK + KTOP];        // 20 values: ss[t+w], t<9, w<12
            #pragma unroll
            for (int i = 0; i < WBLK + KTOP; i++)
                ss[i] = selq[c * DFEAT + w0 + i];     // warp broadcast
            #pragma unroll
            for (int t = 0; t < 9; t++) {
                ull wv = wq[(c * 9 + t) * NPAIRS + pair];   // 256B contig/warp
                #pragma unroll
                for (int w = 0; w < WBLK; w++)
                    FMA2(acc[w], wv, ss[t + w]);
            }
        }

        // epilogue: split pair lanes, add bias, 3x float4 per o-row
        float* op = out + ((size_t)(n0 + nd) * OUTCH + o) * LOUT + w0;
        float rlo[WBLK], rhi[WBLK];
        #pragma unroll
        for (int w = 0; w < WBLK; w++) {
            rlo[w] = __uint_as_float((unsigned)(acc[w]      )) + blo;
            rhi[w] = __uint_as_float((unsigned)(acc[w] >> 32)) + bhi;
        }
        #pragma unroll
        for (int q = 0; q < 3; q++) {
            *(float4*)(op + 4 * q) =
                make_float4(rlo[4*q], rlo[4*q+1], rlo[4*q+2], rlo[4*q+3]);
            *(float4*)(op + LOUT + 4 * q) =
                make_float4(rhi[4*q], rhi[4*q+1], rhi[4*q+2], rhi[4*q+3]);
        }
    }
}

extern "C" void kernel_launch(void* const* d_in, const int* in_sizes, int n_in,
                              void* d_out, int out_size) {
    const float* nf  = (const float*)d_in[0];   // node_features [10000,128] f32
    const int*   adj = (const int*)d_in[1];     // adj_matrix [10000,10000] i32
    const float* w   = (const float*)d_in[2];   // conv_w [128,9,9] f32
    const float* b   = (const float*)d_in[3];   // conv_b [128] f32
    float* out = (float*)d_out;                 // [10000,128,120] f32

    pack_weights_kernel<<<(CT * NPAIRS + 255) / 256, 256>>>(w);
    gather_topk_kernel<<<NNODES / 2, 256>>>(nf, adj);

    const int smem_bytes = (CT * NPAIRS + 2 * 9 * DFEAT) * (int)sizeof(float2);
    cudaFuncSetAttribute(conv_kernel,
                         cudaFuncAttributeMaxDynamicSharedMemorySize, smem_bytes);
    conv_kernel<<<NNODES / 2, CONV_THREADS, smem_bytes>>>(b, out);
}

// round 12
// speedup vs baseline: 1.3076x; 1.0066x over previous
#include <cuda_runtime.h>
#include <cuda_bf16.h>
#include <mma.h>
#include <cstdint>
#include <cstddef>

using namespace nvcuda;

// ---------------- problem constants ----------------
#define NNODES 10000
#define DFEAT  128
#define KTOP   8
#define ROWI4  2500
#define OUTCH  128
#define LOUT   120
#define K81    81
#define K96    96            // K padded for 16-tiles
#define WLDM   104           // W staging ldm (bf16 elems), mult of 8
#define SLDM   136           // S staging ldm (bf16 elems), 272B rows (17x16B)
#define NKT    6             // K tiles
#define NNT    8             // N tiles (120 -> 128 pad)
#define CONVGRID 148

typedef unsigned int u32;
typedef unsigned short u16;

// ---------------- device scratch ----------------
__device__ u16 g_whi[OUTCH * WLDM];                    // Whi [o][ct<104] bf16
__device__ u16 g_wlo[OUTCH * WLDM];
__device__ u16 g_ph[(size_t)NNODES * 9 * DFEAT];       // sel hi planes [n][c][f]
__device__ u16 g_pl[(size_t)NNODES * 9 * DFEAT];       // sel lo planes

// ---------------- bf16 split helpers ----------------
__device__ __forceinline__ u16 bf_hi(float v) {
    return __bfloat16_as_ushort(__float2bfloat16_rn(v));
}
__device__ __forceinline__ u16 bf_lo(float v) {
    float h = __bfloat162float(__float2bfloat16_rn(v));
    return __bfloat16_as_ushort(__float2bfloat16_rn(v - h));
}

// ---------------------------------------------------------------------------
// Kernel 1: pack W into bf16 hi/lo tables [128][104], dense ct = c*9+t
// ---------------------------------------------------------------------------
__global__ void pack_w_kernel(const float* __restrict__ w) {
    int i = blockIdx.x * blockDim.x + threadIdx.x;
    if (i >= OUTCH * WLDM) return;
    int o  = i / WLDM;
    int ct = i - o * WLDM;
    float v = (ct < K81) ? w[o * K81 + ct] : 0.0f;
    g_whi[i] = bf_hi(v);
    g_wlo[i] = bf_lo(v);
}

// branchless sorted-descending top-8 insert
#define TK_INSERT(val) do {                           \
    float _v = (val);                                 \
    _Pragma("unroll")                                 \
    for (int _i = 0; _i < KTOP; _i++) {               \
        float _mx = fmaxf(tk[_i], _v);                \
        _v = fminf(tk[_i], _v);                       \
        tk[_i] = _mx;                                 \
    }                                                 \
} while (0)

// ---------------------------------------------------------------------------
// Kernel 2: adjacency scan + per-feature top-8 -> bf16 hi/lo planes [9][128]
// ---------------------------------------------------------------------------
__global__ __launch_bounds__(256)
void gather_topk_kernel(const float* __restrict__ nf,
                        const int*   __restrict__ adj) {
    __shared__ int snbr[2][64];
    __shared__ int scnt[2];

    const int tid  = threadIdx.x;
    const int half = tid >> 7;
    const int lt   = tid & 127;
    const int n    = blockIdx.x * 2 + half;

    if (lt == 0) scnt[half] = 0;
    __syncthreads();

    const int4* row = (const int4*)(adj + (size_t)n * NNODES);
    for (int i = lt; i < ROWI4; i += 128) {
        int4 q = row[i];
        if (q.x | q.y | q.z | q.w) {
            if (q.x) { int s = atomicAdd(&scnt[half], 1); if (s < 64) snbr[half][s] = (i << 2); }
            if (q.y) { int s = atomicAdd(&scnt[half], 1); if (s < 64) snbr[half][s] = (i << 2) + 1; }
            if (q.z) { int s = atomicAdd(&scnt[half], 1); if (s < 64) snbr[half][s] = (i << 2) + 2; }
            if (q.w) { int s = atomicAdd(&scnt[half], 1); if (s < 64) snbr[half][s] = (i << 2) + 3; }
        }
    }
    __syncthreads();

    int cnt = scnt[half];
    if (cnt > 64) cnt = 64;

    const int f = lt;
    const float NEG_INF = __int_as_float(0xff800000u);
    float tk[KTOP];
    #pragma unroll
    for (int r = 0; r < KTOP; r++) tk[r] = NEG_INF;

    int j = 0;
    for (; j + 4 <= cnt; j += 4) {
        int i0 = snbr[half][j], i1 = snbr[half][j + 1];
        int i2 = snbr[half][j + 2], i3 = snbr[half][j + 3];
        float v0 = __ldg(nf + (size_t)i0 * DFEAT + f);
        float v1 = __ldg(nf + (size_t)i1 * DFEAT + f);
        float v2 = __ldg(nf + (size_t)i2 * DFEAT + f);
        float v3 = __ldg(nf + (size_t)i3 * DFEAT + f);
        TK_INSERT(v0); TK_INSERT(v1); TK_INSERT(v2); TK_INSERT(v3);
    }
    for (; j < cnt; j++) {
        float v = __ldg(nf + (size_t)snbr[half][j] * DFEAT + f);
        TK_INSERT(v);
    }
    for (int z = cnt; z < KTOP; z++) { TK_INSERT(0.0f); }

    float ch[9];
    ch[0] = nf[(size_t)n * DFEAT + f];
    #pragma unroll
    for (int r = 0; r < KTOP; r++) ch[r + 1] = tk[r];

    u16* ph = g_ph + (size_t)n * (9 * DFEAT);
    u16* pl = g_pl + (size_t)n * (9 * DFEAT);
    #pragma unroll
    for (int c = 0; c < 9; c++) {
        ph[c * DFEAT + f] = bf_hi(ch[c]);
        pl[c * DFEAT + f] = bf_lo(ch[c]);
    }
}

// ---------------------------------------------------------------------------
// Kernel 3: persistent WMMA conv. 148 CTAs x 256 threads (8 warps).
// warp = one 16-row o-tile, accumulates all 8 n-tiles across 6 k-tiles,
// 3 bf16-split mma per (kt, nt). S built via im2col from planes (parity trick).
// ---------------------------------------------------------------------------
// smem byte offsets (all mult of 32)
#define OFF_WHI   0
#define OFF_WLO   26624
#define OFF_SHI   53248            // 96 x 272B = 26112
#define OFF_SLO   79360
#define OFF_PH    105472           // 2304 B (9 x 64 u32)
#define OFF_PL    107776
#define OFF_BT    110080           // btile [128][16] f32 = 8192
#define OFF_SCR   118272           // scratch 8 x 16 x 16 f32 = 8192
#define SMEMB     126464

extern __shared__ unsigned char smraw[];

__global__ __launch_bounds__(256, 1)
void conv_wmma_kernel(const float* __restrict__ bias,
                      float*       __restrict__ out) {
    const int tid  = threadIdx.x;
    const int warp = tid >> 5;
    const int lane = tid & 31;

    __nv_bfloat16* sWhi = (__nv_bfloat16*)(smraw + OFF_WHI);
    __nv_bfloat16* sWlo = (__nv_bfloat16*)(smraw + OFF_WLO);
    __nv_bfloat16* sShi = (__nv_bfloat16*)(smraw + OFF_SHI);
    __nv_bfloat16* sSlo = (__nv_bfloat16*)(smraw + OFF_SLO);
    u32*   ph32 = (u32*)(smraw + OFF_PH);
    u32*   pl32 = (u32*)(smraw + OFF_PL);
    float* btile = (float*)(smraw + OFF_BT);
    float* scr   = (float*)(smraw + OFF_SCR);

    // ---- one-time block setup ----
    // stage W hi/lo (u32 copies; smem layout == global layout)
    {
        const u32* gh = (const u32*)g_whi;
        const u32* gl = (const u32*)g_wlo;
        u32* sh = (u32*)sWhi;
        u32* sl = (u32*)sWlo;
        for (int i = tid; i < OUTCH * WLDM / 2; i += 256) {
            sh[i] = gh[i];
            sl[i] = gl[i];
        }
    }
    // zero S (pad rows 81..95 and cols 120..127 stay zero forever)
    {
        u32* s = (u32*)sShi;         // SHI and SLO contiguous: 2*26112 bytes
        for (int i = tid; i < 2 * K96 * SLDM / 2; i += 256) s[i] = 0;
    }
    // bias tile: btile[o][j] = bias[o]
    for (int i = tid; i < OUTCH * 16; i += 256) btile[i] = __ldg(bias + (i >> 4));
    __syncthreads();

    // per-warp bias fragment (acc init)
    wmma::fragment<wmma::accumulator, 16, 16, 16, float> bfrag;
    wmma::load_matrix_sync(bfrag, btile + warp * 16 * 16, 16, wmma::mem_row_major);

    for (int n = blockIdx.x; n < NNODES; n += CONVGRID) {
        // ---- load planes (u32 view) ----
        {
            const u32* gh = (const u32*)g_ph + (size_t)n * 576;
            const u32* gl = (const u32*)g_pl + (size_t)n * 576;
            for (int i = tid; i < 576; i += 256) {
                ph32[i] = __ldg(gh + i);
                pl32[i] = __ldg(gl + i);
            }
        }
        __syncthreads();

        // ---- im2col build: S[ct][w] = sel[c][w + t], bf16 pairs along w ----
        #pragma unroll
        for (int h = 0; h < 2; h++) {
            const u32* p = h ? pl32 : ph32;
            u16* S = h ? (u16*)sSlo : (u16*)sShi;
            for (int idx = tid; idx < K81 * 60; idx += 256) {
                int ct = idx / 60;
                int wp = idx - ct * 60;
                int w  = wp << 1;
                int c  = (ct * 57) >> 9;       // ct/9 for ct<96 (57/512 trick)
                int t  = ct - c * 9;
                int f  = w + t;
                u32 word;
                if (t & 1)
                    word = __funnelshift_r(p[c * 64 + (f >> 1)],
                                           p[c * 64 + (f >> 1) + 1], 16);
                else
                    word = p[c * 64 + (f >> 1)];
                *(u32*)(S + ct * SLDM + w) = word;
            }
        }
        __syncthreads();

        // ---- GEMM: 8 warps x (6 kt x 8 nt x 3 mma) ----
        wmma::fragment<wmma::accumulator, 16, 16, 16, float> acc[NNT];
        #pragma unroll
        for (int nt = 0; nt < NNT; nt++) acc[nt] = bfrag;

        #pragma unroll
        for (int kt = 0; kt < NKT; kt++) {
            wmma::fragment<wmma::matrix_a, 16, 16, 16, __nv_bfloat16, wmma::row_major> ahi, alo;
            wmma::load_matrix_sync(ahi, sWhi + warp * 16 * WLDM + kt * 16, WLDM);
            wmma::load_matrix_sync(alo, sWlo + warp * 16 * WLDM + kt * 16, WLDM);
            #pragma unroll
            for (int nt = 0; nt < NNT; nt++) {
                wmma::fragment<wmma::matrix_b, 16, 16, 16, __nv_bfloat16, wmma::row_major> bhi, blo;
                wmma::load_matrix_sync(bhi, sShi + kt * 16 * SLDM + nt * 16, SLDM);
                wmma::load_matrix_sync(blo, sSlo + kt * 16 * SLDM + nt * 16, SLDM);
                wmma::mma_sync(acc[nt], ahi, bhi, acc[nt]);
                wmma::mma_sync(acc[nt], ahi, blo, acc[nt]);
                wmma::mma_sync(acc[nt], alo, bhi, acc[nt]);
            }
        }

        // ---- epilogue ----
        float* ob = out + ((size_t)n * OUTCH + warp * 16) * LOUT;
        #pragma unroll
        for (int nt = 0; nt < 7; nt++)
            wmma::store_matrix_sync(ob + nt * 16, acc[nt], LOUT, wmma::mem_row_major);
        // partial last tile (w 112..119) via warp-private scratch
        wmma::store_matrix_sync(scr + warp * 256, acc[7], 16, wmma::mem_row_major);
        __syncwarp();
        for (int e = lane; e < 128; e += 32) {
            int r = e >> 3, cw = e & 7;
            ob[r * LOUT + 112 + cw] = scr[warp * 256 + r * 16 + cw];
        }
        __syncthreads();   // S / planes safe to rebuild next iteration
    }
}

// ---------------------------------------------------------------------------
extern "C" void kernel_launch(void* const* d_in, const int* in_sizes, int n_in,
                              void* d_out, int out_size) {
    const float* nf  = (const float*)d_in[0];   // [10000,128] f32
    const int*   adj = (const int*)d_in[1];     // [10000,10000] i32
    const float* w   = (const float*)d_in[2];   // [128,9,9] f32
    const float* b   = (const float*)d_in[3];   // [128] f32
    float* out = (float*)d_out;                 // [10000,128,120] f32

    pack_w_kernel<<<(OUTCH * WLDM + 255) / 256, 256>>>(w);
    gather_topk_kernel<<<NNODES / 2, 256>>>(nf, adj);

    cudaFuncSetAttribute(conv_wmma_kernel,
                         cudaFuncAttributeMaxDynamicSharedMemorySize, SMEMB);
    conv_wmma_kernel<<<CONVGRID, 256, SMEMB>>>(b, out);
}